// round 11
// baseline (speedup 1.0000x reference)
#include <cuda_runtime.h>
#include <math.h>

#define BB 64
#define DD 256
#define NN 16
#define RR 16

// Scratch + sink (device globals: no allocation allowed)
__device__ float g_x1c[BB * DD];
__device__ float g_res1[BB * DD];
__device__ float g_x2c[BB * DD];
__device__ float g_sink[1024];

__device__ __forceinline__ float warp_sum(float v) {
#pragma unroll
    for (int off = 16; off; off >>= 1)
        v += __shfl_xor_sync(0xffffffffu, v, off);
    return v;
}

__device__ __forceinline__ void red4(float& a0, float& a1, float& a2, float& a3) {
#pragma unroll
    for (int off = 16; off; off >>= 1) {
        a0 += __shfl_xor_sync(0xffffffffu, a0, off);
        a1 += __shfl_xor_sync(0xffffffffu, a1, off);
        a2 += __shfl_xor_sync(0xffffffffu, a2, off);
        a3 += __shfl_xor_sync(0xffffffffu, a3, off);
    }
}

__device__ __forceinline__ void red2(float& a0, float& a1) {
#pragma unroll
    for (int off = 16; off; off >>= 1) {
        a0 += __shfl_xor_sync(0xffffffffu, a0, off);
        a1 += __shfl_xor_sync(0xffffffffu, a1, off);
    }
}

__device__ __forceinline__ float dot8(float4 a, float4 b, float4 wa, float4 wb) {
    return a.x * wa.x + a.y * wa.y + a.z * wa.z + a.w * wa.w +
           b.x * wb.x + b.y * wb.y + b.z * wb.z + b.w * wb.w;
}

__device__ __forceinline__ float silu(float v) {
    return __fdividef(v, 1.0f + __expf(-v));
}

// ---------------------------------------------------------------------------
// K1: rmsnorm + in-projection. 768 blocks x 256 threads.
// Block = one output column; warp = 8 batches (2 ILP4 dot groups).
// Also warms L2 with K2's weights (out_w, xproj_w, dt_w, A_log).
// ---------------------------------------------------------------------------
__global__ __launch_bounds__(256) void k_inproj(
    const float* __restrict__ x1, const float* __restrict__ x2,
    const float* __restrict__ norm_w, const float* __restrict__ in_w,
    const float* __restrict__ xproj_w, const float* __restrict__ dt_w,
    const float* __restrict__ A_log, const float* __restrict__ out_w)
{
    __shared__ float s_sc[BB];

    const int tid  = threadIdx.x;
    const int lane = tid & 31;
    const int warp = tid >> 5;
    const int col  = blockIdx.x;               // 0..767

    // --- L2-warm prefetch for K2 (fire loads now, consume at the end) ---
    float pf = 0.0f;
    bool  pf_on = false;
    if (warp == 0) {
        int idx = col * 22 + lane;
        if (lane < 22 && idx < 16384) {        // out_w: 16384 float4
            float4 v = ((const float4*)out_w)[idx];
            pf = v.x + v.y + v.z + v.w; pf_on = true;
        }
    } else if (warp == 1) {
        if (col < 96) {                        // xproj_w: 3072 float4
            float4 v = ((const float4*)xproj_w)[col * 32 + lane];
            pf = v.x + v.y + v.z + v.w; pf_on = true;
        } else if (col < 128) {                // dt_w: 1024 float4
            float4 v = ((const float4*)dt_w)[(col - 96) * 32 + lane];
            pf = v.x + v.y + v.z + v.w; pf_on = true;
        } else if (col < 160) {                // A_log: 1024 float4
            float4 v = ((const float4*)A_log)[(col - 128) * 32 + lane];
            pf = v.x + v.y + v.z + v.w; pf_on = true;
        }
    }

    const float* src = (col < 512) ? x1 : x2;
    const int row    = (col < 512) ? col : (col - 512);

    // rmsnorm scales for the 64 batches of this source (8 warps x 8 rows, ILP4)
#pragma unroll
    for (int g = 0; g < 2; g++) {
        int r0 = warp * 8 + g * 4;
        float a[4];
#pragma unroll
        for (int i = 0; i < 4; i++) {
            const float4* p = (const float4*)(src + (r0 + i) * DD);
            float4 xa = p[lane], xb = p[lane + 32];
            a[i] = dot8(xa, xb, xa, xb);
        }
        red4(a[0], a[1], a[2], a[3]);
        if (lane < 4) {
            float s = (lane == 0) ? a[0] : (lane == 1) ? a[1] : (lane == 2) ? a[2] : a[3];
            s_sc[r0 + lane] = rsqrtf(s * (1.0f / DD) + 1e-5f);
        }
    }

    // Weight column folded with norm_w
    const float4* wr = (const float4*)(in_w + row * DD);
    float4 w0 = wr[lane], w1 = wr[lane + 32];
    const float4* nwp = (const float4*)norm_w;
    float4 n0 = nwp[lane], n1 = nwp[lane + 32];
    w0.x *= n0.x; w0.y *= n0.y; w0.z *= n0.z; w0.w *= n0.w;
    w1.x *= n1.x; w1.y *= n1.y; w1.z *= n1.z; w1.w *= n1.w;

    float* dst;
    int cl;
    if (col < 256)      { dst = g_x1c;  cl = col; }
    else if (col < 512) { dst = g_res1; cl = col - 256; }
    else                { dst = g_x2c;  cl = col - 512; }

    __syncthreads();

    // dots: 8 batches per warp, 2 ILP4 groups
#pragma unroll
    for (int g = 0; g < 2; g++) {
        int b0 = warp * 8 + g * 4;
        float acc[4];
#pragma unroll
        for (int i = 0; i < 4; i++) {
            const float4* xr = (const float4*)(src + (b0 + i) * DD);
            float4 xa = xr[lane], xb = xr[lane + 32];
            acc[i] = dot8(xa, xb, w0, w1);
        }
        red4(acc[0], acc[1], acc[2], acc[3]);
        if (lane < 4) {
            int bb = b0 + lane;
            float v = (lane == 0) ? acc[0] : (lane == 1) ? acc[1] : (lane == 2) ? acc[2] : acc[3];
            dst[bb * DD + cl] = v * s_sc[bb];
        }
    }

    // consume prefetch (keeps the loads alive; condition is never true in practice)
    if (pf_on && pf == 1.2345678e30f) g_sink[col & 1023] = pf;
}

// ---------------------------------------------------------------------------
// K2: one block per batch, 1024 threads (32 warps).
// conv+silu -> xproj (6 dots/warp) -> dt+softplus -> closed-form scan
// (n split over 4 quarters) -> gate -> out-proj (8 dots/warp) -> rmsnorm.
// ---------------------------------------------------------------------------
__global__ __launch_bounds__(1024, 1) void k_scan_out(
    const float* __restrict__ norm_w,
    const float* __restrict__ conv_w, const float* __restrict__ conv_b,
    const float* __restrict__ xproj_w,
    const float* __restrict__ dt_w, const float* __restrict__ dt_b,
    const float* __restrict__ out_w,
    const float* __restrict__ A_log, const float* __restrict__ Dvec,
    const int* __restrict__ lp,
    float* __restrict__ out)
{
    const int b    = blockIdx.x;
    const int t    = threadIdx.x;
    const int ch   = t & 255;
    const int q    = t >> 8;       // quarter 0..3
    const int lane = t & 31;
    const int warp = t >> 5;       // 0..31

    __shared__ __align__(16) float s_x2s[4][DD];
    __shared__ float s_B[4][NN];
    __shared__ float s_Cs[NN];
    __shared__ float s_draw[4][NN];
    __shared__ __align__(16) float s_yp[4 * DD];
    __shared__ __align__(16) float s_y[DD];
    __shared__ __align__(16) float s_out[DD];
    __shared__ float s_red[8];

    // --- conv + silu: 4 distinct timeslots (suffix sums of k=4 kernel) ---
    const float4 cw = ((const float4*)conv_w)[ch];
    const float  cb = conv_b[ch];
    const float S0 = cw.w;
    const float S1 = cw.z + S0;
    const float S2 = cw.y + S1;
    const float S3 = cw.x + S2;
    const float x1cv = g_x1c[b * DD + ch];
    float x1r[4];
    x1r[0] = silu(x1cv * S0 + cb);
    x1r[1] = silu(x1cv * S1 + cb);
    x1r[2] = silu(x1cv * S2 + cb);
    x1r[3] = silu(x1cv * S3 + cb);
    if (q == 0) {
        const float x2cv = g_x2c[b * DD + ch];
        s_x2s[0][ch] = silu(x2cv * S0 + cb);
        s_x2s[1][ch] = silu(x2cv * S1 + cb);
        s_x2s[2][ch] = silu(x2cv * S2 + cb);
        s_x2s[3][ch] = silu(x2cv * S3 + cb);
    }
    __syncthreads();

    // --- xproj: 192 dots over 32 warps = 6 each (group of 4 + group of 2) ---
    {
        float acc[4];
#pragma unroll
        for (int i = 0; i < 4; i++) {
            const int j = warp * 6 + i;
            const int ts = j / 48, c = j % 48;
            const float4* wr = (const float4*)(xproj_w + c * DD);
            const float4* xr = (const float4*)(s_x2s[ts]);
            acc[i] = dot8(xr[lane], xr[lane + 32], wr[lane], wr[lane + 32]);
        }
        red4(acc[0], acc[1], acc[2], acc[3]);
        if (lane < 4) {
            const int j = warp * 6 + lane;
            const int ts = j / 48, c = j % 48;
            float v = (lane == 0) ? acc[0] : (lane == 1) ? acc[1]
                    : (lane == 2) ? acc[2] : acc[3];
            if (c < 16)       s_draw[ts][c]   = v;
            else if (c < 32)  s_B[ts][c - 16] = v;
            else if (ts == 3) s_Cs[c - 32]    = v;
        }
        float a0, a1;
        {
            const int j0 = warp * 6 + 4;
            const int ts0 = j0 / 48, c0 = j0 % 48;
            const float4* wr0 = (const float4*)(xproj_w + c0 * DD);
            const float4* xr0 = (const float4*)(s_x2s[ts0]);
            a0 = dot8(xr0[lane], xr0[lane + 32], wr0[lane], wr0[lane + 32]);
            const int j1 = warp * 6 + 5;
            const int ts1 = j1 / 48, c1 = j1 % 48;
            const float4* wr1 = (const float4*)(xproj_w + c1 * DD);
            const float4* xr1 = (const float4*)(s_x2s[ts1]);
            a1 = dot8(xr1[lane], xr1[lane + 32], wr1[lane], wr1[lane + 32]);
        }
        red2(a0, a1);
        if (lane < 2) {
            const int j = warp * 6 + 4 + lane;
            const int ts = j / 48, c = j % 48;
            float v = (lane == 0) ? a0 : a1;
            if (c < 16)       s_draw[ts][c]   = v;
            else if (c < 32)  s_B[ts][c - 16] = v;
            else if (ts == 3) s_Cs[c - 32]    = v;
        }
    }
    __syncthreads();

    // --- delta = softplus(draw @ dt_w.T + dt_b); u = delta * x1s ---
    float dts[4], u[4];
    {
        float dw[16];
        const float4* p = (const float4*)(dt_w + ch * RR);
        ((float4*)dw)[0] = p[0]; ((float4*)dw)[1] = p[1];
        ((float4*)dw)[2] = p[2]; ((float4*)dw)[3] = p[3];
        const float dtb = dt_b[ch];
#pragma unroll
        for (int ts = 0; ts < 4; ts++) {
            float acc = dtb;
#pragma unroll
            for (int r = 0; r < 16; r++) acc += s_draw[ts][r] * dw[r];
            dts[ts] = (acc > 20.0f) ? acc : log1pf(__expf(acc));
            u[ts]   = dts[ts] * x1r[ts];
        }
    }

    // --- closed-form scan: quarter q handles n in [q*4, q*4+4) ---
    {
        const int l = lp ? *lp : 256;
        const float m = (float)(l - 3);
        float alr[4];
        *((float4*)alr) = *((const float4*)(A_log + ch * NN + q * 4));
        float y = 0.0f;
#pragma unroll
        for (int n = 0; n < 4; n++) {
            const int ng = q * 4 + n;
            float a  = -__expf(alr[n]);
            float e1 = __expf(dts[1] * a);
            float e2 = __expf(dts[2] * a);
            float e3 = __expf(dts[3] * a);
            float h = u[0] * s_B[0][ng];
            h = e1 * h + u[1] * s_B[1][ng];
            h = e2 * h + u[2] * s_B[2][ng];
            float p3 = __expf(m * dts[3] * a);
            float gg = 1.0f - e3;
            float geo = (gg > 1e-30f) ? __fdividef(1.0f - p3, gg) : m;
            h = p3 * h + u[3] * s_B[3][ng] * geo;
            y += h * s_Cs[ng];
        }
        s_yp[t] = y;
    }
    __syncthreads();

    if (q == 0) {
        float yy = s_yp[ch] + s_yp[ch + 256] + s_yp[ch + 512] + s_yp[ch + 768]
                 + x1r[3] * Dvec[ch];
        const float res = g_res1[b * DD + ch];
        yy *= silu(res);
        s_y[ch] = yy;
    }
    __syncthreads();

    // --- out-proj: 256 dots over 32 warps = 8 each, 2 ILP4 groups ---
    {
        const float4* yp4 = (const float4*)s_y;
        const float4 ya = yp4[lane], yb = yp4[lane + 32];
#pragma unroll
        for (int g = 0; g < 2; g++) {
            float acc[4];
#pragma unroll
            for (int i = 0; i < 4; i++) {
                const int c = warp * 8 + g * 4 + i;
                const float4* wr = (const float4*)(out_w + c * DD);
                acc[i] = dot8(ya, yb, wr[lane], wr[lane + 32]);
            }
            red4(acc[0], acc[1], acc[2], acc[3]);
            if (lane < 4) {
                const int c = warp * 8 + g * 4 + lane;
                s_out[c] = (lane == 0) ? acc[0] : (lane == 1) ? acc[1]
                         : (lane == 2) ? acc[2] : acc[3];
            }
        }
    }
    __syncthreads();

    // --- final rmsnorm over d, write output row (quarter 0) ---
    if (q == 0) {
        float v = s_out[ch];
        float ss = warp_sum(v * v);
        if (lane == 0) s_red[warp] = ss;
    }
    __syncthreads();
    if (q == 0) {
        float tot = 0.0f;
#pragma unroll
        for (int w = 0; w < 8; w++) tot += s_red[w];
        float scale = rsqrtf(tot * (1.0f / DD) + 1e-5f);
        out[b * DD + ch] = s_out[ch] * scale * norm_w[ch];
    }
}

// ---------------------------------------------------------------------------
extern "C" void kernel_launch(void* const* d_in, const int* in_sizes, int n_in,
                              void* d_out, int out_size) {
    (void)in_sizes; (void)out_size;
    const float* x1      = (const float*)d_in[0];
    const float* x2      = (const float*)d_in[1];
    const float* norm_w  = (const float*)d_in[2];
    const float* conv_w  = (const float*)d_in[3];
    const float* conv_b  = (const float*)d_in[4];
    const float* in_w    = (const float*)d_in[5];
    const float* xproj_w = (const float*)d_in[6];
    const float* dt_w    = (const float*)d_in[7];
    const float* dt_b    = (const float*)d_in[8];
    const float* out_w   = (const float*)d_in[9];
    const float* A_log   = (const float*)d_in[10];
    const float* Dv      = (const float*)d_in[11];
    const int*   lp      = (n_in > 12) ? (const int*)d_in[12] : nullptr;
    float* out = (float*)d_out;

    k_inproj<<<768, 256>>>(x1, x2, norm_w, in_w, xproj_w, dt_w, A_log, out_w);
    k_scan_out<<<BB, 1024>>>(norm_w, conv_w, conv_b, xproj_w, dt_w, dt_b,
                             out_w, A_log, Dv, lp, out);
}

// round 12
// speedup vs baseline: 1.2174x; 1.2174x over previous
#include <cuda_runtime.h>
#include <math.h>

#define BB 64
#define DD 256
#define NN 16
#define RR 16

// Scratch (device globals: no allocation allowed)
__device__ float g_x1c[BB * DD];
__device__ float g_res1[BB * DD];
__device__ float g_x2c[BB * DD];

__device__ __forceinline__ float warp_sum(float v) {
#pragma unroll
    for (int off = 16; off; off >>= 1)
        v += __shfl_xor_sync(0xffffffffu, v, off);
    return v;
}

__device__ __forceinline__ void red4(float& a0, float& a1, float& a2, float& a3) {
#pragma unroll
    for (int off = 16; off; off >>= 1) {
        a0 += __shfl_xor_sync(0xffffffffu, a0, off);
        a1 += __shfl_xor_sync(0xffffffffu, a1, off);
        a2 += __shfl_xor_sync(0xffffffffu, a2, off);
        a3 += __shfl_xor_sync(0xffffffffu, a3, off);
    }
}

__device__ __forceinline__ void red2(float& a0, float& a1) {
#pragma unroll
    for (int off = 16; off; off >>= 1) {
        a0 += __shfl_xor_sync(0xffffffffu, a0, off);
        a1 += __shfl_xor_sync(0xffffffffu, a1, off);
    }
}

__device__ __forceinline__ float dot8(float4 a, float4 b, float4 wa, float4 wb) {
    return a.x * wa.x + a.y * wa.y + a.z * wa.z + a.w * wa.w +
           b.x * wb.x + b.y * wb.y + b.z * wb.z + b.w * wb.w;
}

__device__ __forceinline__ float dot4(float4 a, float4 b) {
    return a.x * b.x + a.y * b.y + a.z * b.z + a.w * b.w;
}

__device__ __forceinline__ float silu(float v) {
    return __fdividef(v, 1.0f + __expf(-v));
}

// ---------------------------------------------------------------------------
// K1: register/smem-tiled GEMM for rmsnorm + in-projection.
// Grid 96 blocks x 256 threads. Block = 16 batches x 32 columns.
// x rows staged+normalized once in shared (kills the 48MB redundant L2 traffic
// of the per-column layout); weight tile XOR-swizzled for conflict-free LDS.128.
// Thread (warp=b-pair, lane=c) accumulates cols for batches (warp, warp+8).
// ---------------------------------------------------------------------------
__global__ __launch_bounds__(256) void k_inproj(
    const float* __restrict__ x1, const float* __restrict__ x2,
    const float* __restrict__ norm_w, const float* __restrict__ in_w)
{
    __shared__ __align__(16) float s_w[32][DD];   // 32KB, XOR-swizzled float4 rows
    __shared__ __align__(16) float s_x[16][DD];   // 16KB

    const int tid  = threadIdx.x;
    const int lane = tid & 31;
    const int warp = tid >> 5;                // 0..7
    const int cg   = blockIdx.x % 24;         // column tile
    const int bg   = blockIdx.x / 24;         // batch tile (0..3)

    const int col0   = cg * 32;               // global col base 0..736
    const float* src = (col0 < 512) ? x1 : x2;
    const int   wrow0 = (col0 < 512) ? col0 : (col0 - 512);

    float4* sw4 = (float4*)s_w;                // [32][64]
    float4* sx4 = (float4*)s_x;                // [16][64]

    // --- stage weight tile (swizzled) and x rows ---
#pragma unroll
    for (int i = 0; i < 8; i++) {
        int idx = tid + i * 256;               // 0..2047
        int r = idx >> 6, k4 = idx & 63;
        float4 v = ((const float4*)in_w)[(wrow0 + r) * 64 + k4];
        sw4[r * 64 + (k4 ^ (r & 7))] = v;
    }
#pragma unroll
    for (int i = 0; i < 4; i++) {
        int idx = tid + i * 256;               // 0..1023
        int r = idx >> 6, k4 = idx & 63;
        sx4[r * 64 + k4] = ((const float4*)src)[(bg * 16 + r) * 64 + k4];
    }
    __syncthreads();

    // --- rmsnorm scales: warp w reduces rows w and w+8 (result in all lanes) ---
    float a0, a1;
    {
        float4 p0 = sx4[warp * 64 + lane],       p1 = sx4[warp * 64 + lane + 32];
        float4 q0 = sx4[(warp + 8) * 64 + lane], q1 = sx4[(warp + 8) * 64 + lane + 32];
        a0 = dot4(p0, p0) + dot4(p1, p1);
        a1 = dot4(q0, q0) + dot4(q1, q1);
    }
    red2(a0, a1);
    const float sc0 = rsqrtf(a0 * (1.0f / DD) + 1e-5f);
    const float sc1 = rsqrtf(a1 * (1.0f / DD) + 1e-5f);

    // --- normalize in place (fold norm_w): thread covers k-range lane*8..+8 ---
    {
        float4 n0 = ((const float4*)norm_w)[lane * 2];
        float4 n1 = ((const float4*)norm_w)[lane * 2 + 1];
        float4 v;
        v = sx4[warp * 64 + lane * 2];
        v.x *= sc0 * n0.x; v.y *= sc0 * n0.y; v.z *= sc0 * n0.z; v.w *= sc0 * n0.w;
        sx4[warp * 64 + lane * 2] = v;
        v = sx4[warp * 64 + lane * 2 + 1];
        v.x *= sc0 * n1.x; v.y *= sc0 * n1.y; v.z *= sc0 * n1.z; v.w *= sc0 * n1.w;
        sx4[warp * 64 + lane * 2 + 1] = v;
        v = sx4[(warp + 8) * 64 + lane * 2];
        v.x *= sc1 * n0.x; v.y *= sc1 * n0.y; v.z *= sc1 * n0.z; v.w *= sc1 * n0.w;
        sx4[(warp + 8) * 64 + lane * 2] = v;
        v = sx4[(warp + 8) * 64 + lane * 2 + 1];
        v.x *= sc1 * n1.x; v.y *= sc1 * n1.y; v.z *= sc1 * n1.z; v.w *= sc1 * n1.w;
        sx4[(warp + 8) * 64 + lane * 2 + 1] = v;
    }
    __syncthreads();

    // --- GEMM: thread = (col c=lane, batches warp & warp+8) ---
    const int c = lane;
    float acc0 = 0.0f, acc1 = 0.0f;
#pragma unroll
    for (int k4 = 0; k4 < 64; k4++) {
        float4 wv = sw4[c * 64 + (k4 ^ (c & 7))];   // conflict-free (swizzle)
        float4 xa = sx4[warp * 64 + k4];            // broadcast
        float4 xb = sx4[(warp + 8) * 64 + k4];      // broadcast
        acc0 += dot4(xa, wv);
        acc1 += dot4(xb, wv);
    }

    // --- store (coalesced: lanes = consecutive cols) ---
    const int col = col0 + c;
    float* dst;
    int cl;
    if (col < 256)      { dst = g_x1c;  cl = col; }
    else if (col < 512) { dst = g_res1; cl = col - 256; }
    else                { dst = g_x2c;  cl = col - 512; }
    dst[(bg * 16 + warp) * DD + cl]     = acc0;
    dst[(bg * 16 + warp + 8) * DD + cl] = acc1;
}

// ---------------------------------------------------------------------------
// K2: one block per batch, 1024 threads (32 warps).
// conv+silu -> xproj (144 needed dots: 1 red4 group/warp + 1 single for 16
// warps) -> dt+softplus -> closed-form scan (4-way n split) -> gate ->
// out-proj (2 ILP4 groups/warp) -> rmsnorm.
// ---------------------------------------------------------------------------
__global__ __launch_bounds__(1024, 1) void k_scan_out(
    const float* __restrict__ norm_w,
    const float* __restrict__ conv_w, const float* __restrict__ conv_b,
    const float* __restrict__ xproj_w,
    const float* __restrict__ dt_w, const float* __restrict__ dt_b,
    const float* __restrict__ out_w,
    const float* __restrict__ A_log, const float* __restrict__ Dvec,
    const int* __restrict__ lp,
    float* __restrict__ out)
{
    const int b    = blockIdx.x;
    const int t    = threadIdx.x;
    const int ch   = t & 255;
    const int q    = t >> 8;       // quarter 0..3
    const int lane = t & 31;
    const int warp = t >> 5;       // 0..31

    __shared__ __align__(16) float s_x2s[4][DD];
    __shared__ float s_B[4][NN];
    __shared__ float s_Cs[NN];
    __shared__ float s_draw[4][NN];
    __shared__ __align__(16) float s_yp[4 * DD];
    __shared__ __align__(16) float s_y[DD];
    __shared__ __align__(16) float s_out[DD];
    __shared__ float s_red[8];

    const int l = lp ? *lp : 256;   // hoisted: latency hidden under phases

    // --- conv + silu: 4 distinct timeslots (suffix sums of k=4 kernel) ---
    const float4 cw = ((const float4*)conv_w)[ch];
    const float  cb = conv_b[ch];
    const float S0 = cw.w;
    const float S1 = cw.z + S0;
    const float S2 = cw.y + S1;
    const float S3 = cw.x + S2;
    const float x1cv = g_x1c[b * DD + ch];
    float x1r[4];
    x1r[0] = silu(x1cv * S0 + cb);
    x1r[1] = silu(x1cv * S1 + cb);
    x1r[2] = silu(x1cv * S2 + cb);
    x1r[3] = silu(x1cv * S3 + cb);
    if (q == 0) {
        const float x2cv = g_x2c[b * DD + ch];
        s_x2s[0][ch] = silu(x2cv * S0 + cb);
        s_x2s[1][ch] = silu(x2cv * S1 + cb);
        s_x2s[2][ch] = silu(x2cv * S2 + cb);
        s_x2s[3][ch] = silu(x2cv * S3 + cb);
    }
    __syncthreads();

    // --- xproj: only 144 needed dots (C used only at steady ts=3).
    // j layout: 0..95  -> ts=j>>5, c=j&31 (delta+B, ts 0..2)
    //           96..143-> ts=3,    c=j-96 (delta+B+C)
#pragma unroll
    {
        float acc[4];
#pragma unroll
        for (int i = 0; i < 4; i++) {
            const int j = warp * 4 + i;              // 0..127
            const int ts = (j < 96) ? (j >> 5) : 3;
            const int c  = (j < 96) ? (j & 31) : (j - 96);
            const float4* wr = (const float4*)(xproj_w + c * DD);
            const float4* xr = (const float4*)(s_x2s[ts]);
            acc[i] = dot8(xr[lane], xr[lane + 32], wr[lane], wr[lane + 32]);
        }
        red4(acc[0], acc[1], acc[2], acc[3]);
        if (lane < 4) {
            const int j = warp * 4 + lane;
            const int ts = (j < 96) ? (j >> 5) : 3;
            const int c  = (j < 96) ? (j & 31) : (j - 96);
            float v = (lane == 0) ? acc[0] : (lane == 1) ? acc[1]
                    : (lane == 2) ? acc[2] : acc[3];
            if (c < 16)       s_draw[ts][c]   = v;
            else if (c < 32)  s_B[ts][c - 16] = v;
            else              s_Cs[c - 32]    = v;
        }
        if (warp < 16) {                              // j = 128..143: ts=3, c=32..47
            const int c = 32 + warp;
            const float4* wr = (const float4*)(xproj_w + c * DD);
            const float4* xr = (const float4*)(s_x2s[3]);
            float a = dot8(xr[lane], xr[lane + 32], wr[lane], wr[lane + 32]);
            a = warp_sum(a);
            if (lane == 0) s_Cs[c - 32] = a;
        }
    }
    __syncthreads();

    // --- delta = softplus(draw @ dt_w.T + dt_b); u = delta * x1s ---
    float dts[4], u[4];
    {
        float dw[16];
        const float4* p = (const float4*)(dt_w + ch * RR);
        ((float4*)dw)[0] = p[0]; ((float4*)dw)[1] = p[1];
        ((float4*)dw)[2] = p[2]; ((float4*)dw)[3] = p[3];
        const float dtb = dt_b[ch];
#pragma unroll
        for (int ts = 0; ts < 4; ts++) {
            float acc = dtb;
#pragma unroll
            for (int r = 0; r < 16; r++) acc += s_draw[ts][r] * dw[r];
            dts[ts] = (acc > 20.0f) ? acc : log1pf(__expf(acc));
            u[ts]   = dts[ts] * x1r[ts];
        }
    }

    // --- closed-form scan: quarter q handles n in [q*4, q*4+4) ---
    {
        const float m = (float)(l - 3);
        float alr[4];
        *((float4*)alr) = *((const float4*)(A_log + ch * NN + q * 4));
        float y = 0.0f;
#pragma unroll
        for (int n = 0; n < 4; n++) {
            const int ng = q * 4 + n;
            float a  = -__expf(alr[n]);
            float e1 = __expf(dts[1] * a);
            float e2 = __expf(dts[2] * a);
            float e3 = __expf(dts[3] * a);
            float h = u[0] * s_B[0][ng];
            h = e1 * h + u[1] * s_B[1][ng];
            h = e2 * h + u[2] * s_B[2][ng];
            float p3 = __expf(m * dts[3] * a);
            float gg = 1.0f - e3;
            float geo = (gg > 1e-30f) ? __fdividef(1.0f - p3, gg) : m;
            h = p3 * h + u[3] * s_B[3][ng] * geo;
            y += h * s_Cs[ng];
        }
        s_yp[t] = y;
    }
    __syncthreads();

    if (q == 0) {
        float yy = s_yp[ch] + s_yp[ch + 256] + s_yp[ch + 512] + s_yp[ch + 768]
                 + x1r[3] * Dvec[ch];
        const float res = g_res1[b * DD + ch];
        yy *= silu(res);
        s_y[ch] = yy;
    }
    __syncthreads();

    // --- out-proj: 256 dots over 32 warps = 8 each, 2 ILP4 groups ---
    {
        const float4* yp4 = (const float4*)s_y;
        const float4 ya = yp4[lane], yb = yp4[lane + 32];
#pragma unroll
        for (int g = 0; g < 2; g++) {
            float acc[4];
#pragma unroll
            for (int i = 0; i < 4; i++) {
                const int c = warp * 8 + g * 4 + i;
                const float4* wr = (const float4*)(out_w + c * DD);
                acc[i] = dot8(ya, yb, wr[lane], wr[lane + 32]);
            }
            red4(acc[0], acc[1], acc[2], acc[3]);
            if (lane < 4) {
                const int c = warp * 8 + g * 4 + lane;
                s_out[c] = (lane == 0) ? acc[0] : (lane == 1) ? acc[1]
                         : (lane == 2) ? acc[2] : acc[3];
            }
        }
    }
    __syncthreads();

    // --- final rmsnorm over d, write output row (quarter 0) ---
    if (q == 0) {
        float v = s_out[ch];
        float ss = warp_sum(v * v);
        if (lane == 0) s_red[warp] = ss;
    }
    __syncthreads();
    if (q == 0) {
        float tot = 0.0f;
#pragma unroll
        for (int w = 0; w < 8; w++) tot += s_red[w];
        float scale = rsqrtf(tot * (1.0f / DD) + 1e-5f);
        out[b * DD + ch] = s_out[ch] * scale * norm_w[ch];
    }
}

// ---------------------------------------------------------------------------
extern "C" void kernel_launch(void* const* d_in, const int* in_sizes, int n_in,
                              void* d_out, int out_size) {
    (void)in_sizes; (void)out_size;
    const float* x1      = (const float*)d_in[0];
    const float* x2      = (const float*)d_in[1];
    const float* norm_w  = (const float*)d_in[2];
    const float* conv_w  = (const float*)d_in[3];
    const float* conv_b  = (const float*)d_in[4];
    const float* in_w    = (const float*)d_in[5];
    const float* xproj_w = (const float*)d_in[6];
    const float* dt_w    = (const float*)d_in[7];
    const float* dt_b    = (const float*)d_in[8];
    const float* out_w   = (const float*)d_in[9];
    const float* A_log   = (const float*)d_in[10];
    const float* Dv      = (const float*)d_in[11];
    const int*   lp      = (n_in > 12) ? (const int*)d_in[12] : nullptr;
    float* out = (float*)d_out;

    k_inproj<<<96, 256>>>(x1, x2, norm_w, in_w);
    k_scan_out<<<BB, 1024>>>(norm_w, conv_w, conv_b, xproj_w, dt_w, dt_b,
                             out_w, A_log, Dv, lp, out);
}

// round 13
// speedup vs baseline: 1.2339x; 1.0136x over previous
#include <cuda_runtime.h>
#include <math.h>

#define BB 64
#define DD 256
#define NN 16
#define RR 16

// Scratch (device globals: no allocation allowed)
__device__ float g_x1c[BB * DD];
__device__ float g_res1[BB * DD];
__device__ float g_x2c[BB * DD];

__device__ __forceinline__ float warp_sum(float v) {
#pragma unroll
    for (int off = 16; off; off >>= 1)
        v += __shfl_xor_sync(0xffffffffu, v, off);
    return v;
}

__device__ __forceinline__ void red4(float& a0, float& a1, float& a2, float& a3) {
#pragma unroll
    for (int off = 16; off; off >>= 1) {
        a0 += __shfl_xor_sync(0xffffffffu, a0, off);
        a1 += __shfl_xor_sync(0xffffffffu, a1, off);
        a2 += __shfl_xor_sync(0xffffffffu, a2, off);
        a3 += __shfl_xor_sync(0xffffffffu, a3, off);
    }
}

__device__ __forceinline__ void red2(float& a0, float& a1) {
#pragma unroll
    for (int off = 16; off; off >>= 1) {
        a0 += __shfl_xor_sync(0xffffffffu, a0, off);
        a1 += __shfl_xor_sync(0xffffffffu, a1, off);
    }
}

__device__ __forceinline__ float dot8(float4 a, float4 b, float4 wa, float4 wb) {
    return a.x * wa.x + a.y * wa.y + a.z * wa.z + a.w * wa.w +
           b.x * wb.x + b.y * wb.y + b.z * wb.z + b.w * wb.w;
}

__device__ __forceinline__ float dot4(float4 a, float4 b) {
    return a.x * b.x + a.y * b.y + a.z * b.z + a.w * b.w;
}

__device__ __forceinline__ float silu(float v) {
    return __fdividef(v, 1.0f + __expf(-v));
}

// ---------------------------------------------------------------------------
// K1: register/smem-tiled GEMM for rmsnorm + in-projection.
// Grid 96 blocks x 256 threads. Block = 16 batches x 32 columns.
// x rows staged+normalized once in shared (kills the 48MB redundant L2 traffic
// of the per-column layout); weight tile XOR-swizzled for conflict-free LDS.128.
// Thread (warp=b-pair, lane=c) accumulates cols for batches (warp, warp+8).
// ---------------------------------------------------------------------------
__global__ __launch_bounds__(256) void k_inproj(
    const float* __restrict__ x1, const float* __restrict__ x2,
    const float* __restrict__ norm_w, const float* __restrict__ in_w)
{
    __shared__ __align__(16) float s_w[32][DD];   // 32KB, XOR-swizzled float4 rows
    __shared__ __align__(16) float s_x[16][DD];   // 16KB

    const int tid  = threadIdx.x;
    const int lane = tid & 31;
    const int warp = tid >> 5;                // 0..7
    const int cg   = blockIdx.x % 24;         // column tile
    const int bg   = blockIdx.x / 24;         // batch tile (0..3)

    const int col0   = cg * 32;               // global col base 0..736
    const float* src = (col0 < 512) ? x1 : x2;
    const int   wrow0 = (col0 < 512) ? col0 : (col0 - 512);

    float4* sw4 = (float4*)s_w;                // [32][64]
    float4* sx4 = (float4*)s_x;                // [16][64]

    // --- stage weight tile (swizzled) and x rows ---
#pragma unroll
    for (int i = 0; i < 8; i++) {
        int idx = tid + i * 256;               // 0..2047
        int r = idx >> 6, k4 = idx & 63;
        float4 v = ((const float4*)in_w)[(wrow0 + r) * 64 + k4];
        sw4[r * 64 + (k4 ^ (r & 7))] = v;
    }
#pragma unroll
    for (int i = 0; i < 4; i++) {
        int idx = tid + i * 256;               // 0..1023
        int r = idx >> 6, k4 = idx & 63;
        sx4[r * 64 + k4] = ((const float4*)src)[(bg * 16 + r) * 64 + k4];
    }
    __syncthreads();

    // --- rmsnorm scales: warp w reduces rows w and w+8 (result in all lanes) ---
    float a0, a1;
    {
        float4 p0 = sx4[warp * 64 + lane],       p1 = sx4[warp * 64 + lane + 32];
        float4 q0 = sx4[(warp + 8) * 64 + lane], q1 = sx4[(warp + 8) * 64 + lane + 32];
        a0 = dot4(p0, p0) + dot4(p1, p1);
        a1 = dot4(q0, q0) + dot4(q1, q1);
    }
    red2(a0, a1);
    const float sc0 = rsqrtf(a0 * (1.0f / DD) + 1e-5f);
    const float sc1 = rsqrtf(a1 * (1.0f / DD) + 1e-5f);

    // --- normalize in place (fold norm_w): thread covers k-range lane*8..+8 ---
    {
        float4 n0 = ((const float4*)norm_w)[lane * 2];
        float4 n1 = ((const float4*)norm_w)[lane * 2 + 1];
        float4 v;
        v = sx4[warp * 64 + lane * 2];
        v.x *= sc0 * n0.x; v.y *= sc0 * n0.y; v.z *= sc0 * n0.z; v.w *= sc0 * n0.w;
        sx4[warp * 64 + lane * 2] = v;
        v = sx4[warp * 64 + lane * 2 + 1];
        v.x *= sc0 * n1.x; v.y *= sc0 * n1.y; v.z *= sc0 * n1.z; v.w *= sc0 * n1.w;
        sx4[warp * 64 + lane * 2 + 1] = v;
        v = sx4[(warp + 8) * 64 + lane * 2];
        v.x *= sc1 * n0.x; v.y *= sc1 * n0.y; v.z *= sc1 * n0.z; v.w *= sc1 * n0.w;
        sx4[(warp + 8) * 64 + lane * 2] = v;
        v = sx4[(warp + 8) * 64 + lane * 2 + 1];
        v.x *= sc1 * n1.x; v.y *= sc1 * n1.y; v.z *= sc1 * n1.z; v.w *= sc1 * n1.w;
        sx4[(warp + 8) * 64 + lane * 2 + 1] = v;
    }
    __syncthreads();

    // --- GEMM: thread = (col c=lane, batches warp & warp+8) ---
    const int c = lane;
    float acc0 = 0.0f, acc1 = 0.0f;
#pragma unroll
    for (int k4 = 0; k4 < 64; k4++) {
        float4 wv = sw4[c * 64 + (k4 ^ (c & 7))];   // conflict-free (swizzle)
        float4 xa = sx4[warp * 64 + k4];            // broadcast
        float4 xb = sx4[(warp + 8) * 64 + k4];      // broadcast
        acc0 += dot4(xa, wv);
        acc1 += dot4(xb, wv);
    }

    // --- store (coalesced: lanes = consecutive cols) ---
    const int col = col0 + c;
    float* dst;
    int cl;
    if (col < 256)      { dst = g_x1c;  cl = col; }
    else if (col < 512) { dst = g_res1; cl = col - 256; }
    else                { dst = g_x2c;  cl = col - 512; }
    dst[(bg * 16 + warp) * DD + cl]     = acc0;
    dst[(bg * 16 + warp + 8) * DD + cl] = acc1;
}

// ---------------------------------------------------------------------------
// K2: one block per batch, 1024 threads (32 warps).
// conv+silu -> xproj (144 needed dots: 1 red4 group/warp + 1 single for 16
// warps) -> dt+softplus -> closed-form scan (4-way n split) -> gate ->
// out-proj (2 ILP4 groups/warp) -> rmsnorm.
// ---------------------------------------------------------------------------
__global__ __launch_bounds__(1024, 1) void k_scan_out(
    const float* __restrict__ norm_w,
    const float* __restrict__ conv_w, const float* __restrict__ conv_b,
    const float* __restrict__ xproj_w,
    const float* __restrict__ dt_w, const float* __restrict__ dt_b,
    const float* __restrict__ out_w,
    const float* __restrict__ A_log, const float* __restrict__ Dvec,
    const int* __restrict__ lp,
    float* __restrict__ out)
{
    const int b    = blockIdx.x;
    const int t    = threadIdx.x;
    const int ch   = t & 255;
    const int q    = t >> 8;       // quarter 0..3
    const int lane = t & 31;
    const int warp = t >> 5;       // 0..31

    __shared__ __align__(16) float s_x2s[4][DD];
    __shared__ float s_B[4][NN];
    __shared__ float s_Cs[NN];
    __shared__ float s_draw[4][NN];
    __shared__ __align__(16) float s_yp[4 * DD];
    __shared__ __align__(16) float s_y[DD];
    __shared__ __align__(16) float s_out[DD];
    __shared__ float s_red[8];

    const int l = lp ? *lp : 256;   // hoisted: latency hidden under phases

    // --- conv + silu: 4 distinct timeslots (suffix sums of k=4 kernel) ---
    const float4 cw = ((const float4*)conv_w)[ch];
    const float  cb = conv_b[ch];
    const float S0 = cw.w;
    const float S1 = cw.z + S0;
    const float S2 = cw.y + S1;
    const float S3 = cw.x + S2;
    const float x1cv = g_x1c[b * DD + ch];
    float x1r[4];
    x1r[0] = silu(x1cv * S0 + cb);
    x1r[1] = silu(x1cv * S1 + cb);
    x1r[2] = silu(x1cv * S2 + cb);
    x1r[3] = silu(x1cv * S3 + cb);
    if (q == 0) {
        const float x2cv = g_x2c[b * DD + ch];
        s_x2s[0][ch] = silu(x2cv * S0 + cb);
        s_x2s[1][ch] = silu(x2cv * S1 + cb);
        s_x2s[2][ch] = silu(x2cv * S2 + cb);
        s_x2s[3][ch] = silu(x2cv * S3 + cb);
    }
    __syncthreads();

    // --- xproj: only 144 needed dots (C used only at steady ts=3).
    // j layout: 0..95  -> ts=j>>5, c=j&31 (delta+B, ts 0..2)
    //           96..143-> ts=3,    c=j-96 (delta+B+C)
#pragma unroll
    {
        float acc[4];
#pragma unroll
        for (int i = 0; i < 4; i++) {
            const int j = warp * 4 + i;              // 0..127
            const int ts = (j < 96) ? (j >> 5) : 3;
            const int c  = (j < 96) ? (j & 31) : (j - 96);
            const float4* wr = (const float4*)(xproj_w + c * DD);
            const float4* xr = (const float4*)(s_x2s[ts]);
            acc[i] = dot8(xr[lane], xr[lane + 32], wr[lane], wr[lane + 32]);
        }
        red4(acc[0], acc[1], acc[2], acc[3]);
        if (lane < 4) {
            const int j = warp * 4 + lane;
            const int ts = (j < 96) ? (j >> 5) : 3;
            const int c  = (j < 96) ? (j & 31) : (j - 96);
            float v = (lane == 0) ? acc[0] : (lane == 1) ? acc[1]
                    : (lane == 2) ? acc[2] : acc[3];
            if (c < 16)       s_draw[ts][c]   = v;
            else if (c < 32)  s_B[ts][c - 16] = v;
            else              s_Cs[c - 32]    = v;
        }
        if (warp < 16) {                              // j = 128..143: ts=3, c=32..47
            const int c = 32 + warp;
            const float4* wr = (const float4*)(xproj_w + c * DD);
            const float4* xr = (const float4*)(s_x2s[3]);
            float a = dot8(xr[lane], xr[lane + 32], wr[lane], wr[lane + 32]);
            a = warp_sum(a);
            if (lane == 0) s_Cs[c - 32] = a;
        }
    }
    __syncthreads();

    // --- delta = softplus(draw @ dt_w.T + dt_b); u = delta * x1s ---
    float dts[4], u[4];
    {
        float dw[16];
        const float4* p = (const float4*)(dt_w + ch * RR);
        ((float4*)dw)[0] = p[0]; ((float4*)dw)[1] = p[1];
        ((float4*)dw)[2] = p[2]; ((float4*)dw)[3] = p[3];
        const float dtb = dt_b[ch];
#pragma unroll
        for (int ts = 0; ts < 4; ts++) {
            float acc = dtb;
#pragma unroll
            for (int r = 0; r < 16; r++) acc += s_draw[ts][r] * dw[r];
            dts[ts] = (acc > 20.0f) ? acc : log1pf(__expf(acc));
            u[ts]   = dts[ts] * x1r[ts];
        }
    }

    // --- closed-form scan: quarter q handles n in [q*4, q*4+4) ---
    {
        const float m = (float)(l - 3);
        float alr[4];
        *((float4*)alr) = *((const float4*)(A_log + ch * NN + q * 4));
        float y = 0.0f;
#pragma unroll
        for (int n = 0; n < 4; n++) {
            const int ng = q * 4 + n;
            float a  = -__expf(alr[n]);
            float e1 = __expf(dts[1] * a);
            float e2 = __expf(dts[2] * a);
            float e3 = __expf(dts[3] * a);
            float h = u[0] * s_B[0][ng];
            h = e1 * h + u[1] * s_B[1][ng];
            h = e2 * h + u[2] * s_B[2][ng];
            float p3 = __expf(m * dts[3] * a);
            float gg = 1.0f - e3;
            float geo = (gg > 1e-30f) ? __fdividef(1.0f - p3, gg) : m;
            h = p3 * h + u[3] * s_B[3][ng] * geo;
            y += h * s_Cs[ng];
        }
        s_yp[t] = y;
    }
    __syncthreads();

    if (q == 0) {
        float yy = s_yp[ch] + s_yp[ch + 256] + s_yp[ch + 512] + s_yp[ch + 768]
                 + x1r[3] * Dvec[ch];
        const float res = g_res1[b * DD + ch];
        yy *= silu(res);
        s_y[ch] = yy;
    }
    __syncthreads();

    // --- out-proj: 256 dots over 32 warps = 8 each, 2 ILP4 groups ---
    {
        const float4* yp4 = (const float4*)s_y;
        const float4 ya = yp4[lane], yb = yp4[lane + 32];
#pragma unroll
        for (int g = 0; g < 2; g++) {
            float acc[4];
#pragma unroll
            for (int i = 0; i < 4; i++) {
                const int c = warp * 8 + g * 4 + i;
                const float4* wr = (const float4*)(out_w + c * DD);
                acc[i] = dot8(ya, yb, wr[lane], wr[lane + 32]);
            }
            red4(acc[0], acc[1], acc[2], acc[3]);
            if (lane < 4) {
                const int c = warp * 8 + g * 4 + lane;
                s_out[c] = (lane == 0) ? acc[0] : (lane == 1) ? acc[1]
                         : (lane == 2) ? acc[2] : acc[3];
            }
        }
    }
    __syncthreads();

    // --- final rmsnorm over d, write output row (quarter 0) ---
    if (q == 0) {
        float v = s_out[ch];
        float ss = warp_sum(v * v);
        if (lane == 0) s_red[warp] = ss;
    }
    __syncthreads();
    if (q == 0) {
        float tot = 0.0f;
#pragma unroll
        for (int w = 0; w < 8; w++) tot += s_red[w];
        float scale = rsqrtf(tot * (1.0f / DD) + 1e-5f);
        out[b * DD + ch] = s_out[ch] * scale * norm_w[ch];
    }
}

// ---------------------------------------------------------------------------
extern "C" void kernel_launch(void* const* d_in, const int* in_sizes, int n_in,
                              void* d_out, int out_size) {
    (void)in_sizes; (void)out_size;
    const float* x1      = (const float*)d_in[0];
    const float* x2      = (const float*)d_in[1];
    const float* norm_w  = (const float*)d_in[2];
    const float* conv_w  = (const float*)d_in[3];
    const float* conv_b  = (const float*)d_in[4];
    const float* in_w    = (const float*)d_in[5];
    const float* xproj_w = (const float*)d_in[6];
    const float* dt_w    = (const float*)d_in[7];
    const float* dt_b    = (const float*)d_in[8];
    const float* out_w   = (const float*)d_in[9];
    const float* A_log   = (const float*)d_in[10];
    const float* Dv      = (const float*)d_in[11];
    const int*   lp      = (n_in > 12) ? (const int*)d_in[12] : nullptr;
    float* out = (float*)d_out;

    k_inproj<<<96, 256>>>(x1, x2, norm_w, in_w);
    k_scan_out<<<BB, 1024>>>(norm_w, conv_w, conv_b, xproj_w, dt_w, dt_b,
                             out_w, A_log, Dv, lp, out);
}